// round 5
// baseline (speedup 1.0000x reference)
#include <cuda_runtime.h>
#include <cuda_fp16.h>
#include <cstdint>

#define N_ 16
#define C_ 256
#define T_ 300
#define V_ 25
#define K_ 3
#define TK_ 9
#define J_ 7500
#define KD1 768            // GEMM1 K-dim (k,ci)
#define BN_EPS 1e-5f

// static device scratch
__device__ __align__(256) __half xa_buf[(size_t)N_ * J_ * KD1];   // 184 MB
__device__ __align__(256) __half gt_buf[(size_t)N_ * J_ * C_];    // 61.4 MB
__device__ __align__(256) __half wt2_buf[TK_ * C_ * C_];          // [dt][co][ci]
__device__ __align__(256) __half wa_buf[C_ * KD1];                // [co][(k,ci)]
__device__ float bcw_buf[C_ * V_];                                // bias*sum(AM)

// ---------------------------------------------------------------------------
// PTX helpers
// ---------------------------------------------------------------------------
__device__ __forceinline__ uint32_t smem_u32(const void* p) {
    uint32_t a;
    asm("{ .reg .u64 t; cvta.to.shared.u64 t, %1; cvt.u32.u64 %0, t; }" : "=r"(a) : "l"(p));
    return a;
}
__device__ __forceinline__ void ldsm4(uint32_t* r, uint32_t addr) {
    asm volatile("ldmatrix.sync.aligned.m8n8.x4.shared.b16 {%0,%1,%2,%3}, [%4];"
                 : "=r"(r[0]), "=r"(r[1]), "=r"(r[2]), "=r"(r[3]) : "r"(addr));
}
__device__ __forceinline__ void mma16816(float* c, const uint32_t* a,
                                         uint32_t b0, uint32_t b1) {
    asm volatile(
        "mma.sync.aligned.m16n8k16.row.col.f32.f16.f16.f32 "
        "{%0,%1,%2,%3}, {%4,%5,%6,%7}, {%8,%9}, {%0,%1,%2,%3};"
        : "+f"(c[0]), "+f"(c[1]), "+f"(c[2]), "+f"(c[3])
        : "r"(a[0]), "r"(a[1]), "r"(a[2]), "r"(a[3]), "r"(b0), "r"(b1));
}
__device__ __forceinline__ void cpa16(uint32_t dst, const void* src, int srcsize) {
    asm volatile("cp.async.cg.shared.global [%0], [%1], 16, %2;"
                 :: "r"(dst), "l"(src), "r"(srcsize));
}
__device__ __forceinline__ void cpa_commit() {
    asm volatile("cp.async.commit_group;" ::: "memory");
}
template <int NN>
__device__ __forceinline__ void cpa_wait() {
    asm volatile("cp.async.wait_group %0;" :: "n"(NN) : "memory");
}

// ---------------------------------------------------------------------------
// prep kernels
// ---------------------------------------------------------------------------
__global__ void wt2_kernel(const float* __restrict__ tw) {
    int i = blockIdx.x * 256 + threadIdx.x;
    if (i < TK_ * C_ * C_) {
        int dt = i / (C_ * C_);
        int r  = i - dt * C_ * C_;
        int co = r >> 8;
        int ci = r & 255;
        wt2_buf[i] = __float2half_rn(tw[(co * C_ + ci) * TK_ + dt]);
    }
}

__global__ void wa_kernel(const float* __restrict__ cw) {
    int i = blockIdx.x * 256 + threadIdx.x;
    if (i < C_ * KD1) {
        int co = i / KD1;
        int kk = i - co * KD1;
        int k  = kk >> 8;
        int ci = kk & 255;
        wa_buf[i] = __float2half_rn(cw[(k * C_ + co) * C_ + ci]);
    }
}

__global__ void bcw_kernel(const float* __restrict__ A, const float* __restrict__ Mm,
                           const float* __restrict__ bias) {
    __shared__ float S[K_ * V_];
    int tid = threadIdx.x;
    if (tid < K_ * V_) {
        int k = tid / V_;
        int w = tid - k * V_;
        float s = 0.f;
        for (int v = 0; v < V_; ++v) {
            int idx = (k * V_ + v) * V_ + w;
            s += A[idx] * Mm[idx];
        }
        S[tid] = s;
    }
    __syncthreads();
    int c = tid;   // 256 threads
    for (int w = 0; w < V_; ++w) {
        float s = 0.f;
        #pragma unroll
        for (int k = 0; k < K_; ++k)
            s += bias[k * C_ + c] * S[k * V_ + w];
        bcw_buf[c * V_ + w] = s;
    }
}

// ---------------------------------------------------------------------------
// xa kernel v2: xa[n][j=(t,w)][(k,ci)] = sum_v x[n,ci,t,v] * (A*M)[k,v,w]
// 384 threads: 12 warps = 3 k x 4 ci-pair chunks; warp lanes = w (25 of 32)
// AM in registers (packed (am,am)); fp32x2 packed FMA; smem-staged output.
// ---------------------------------------------------------------------------
#define XA_THREADS 384
#define HSTRIDE 776          // hout row stride in halfs (16B multiple)
#define XA_SMEM (6400*4 + 1880*4 + V_*HSTRIDE*2)   // 25600+7520+38800 = 71920

__global__ void __launch_bounds__(XA_THREADS, 2) xa_kernel(
    const float* __restrict__ x, const float* __restrict__ A,
    const float* __restrict__ Mm)
{
    extern __shared__ float sxa[];
    float*  xsp  = sxa;                    // [128 pairs][25 v][2]
    float*  ams  = sxa + 6400;             // [k][v][w] (padded to 1880)
    __half* hout = (__half*)(sxa + 6400 + 1880);   // [25 w][HSTRIDE]

    const int t    = blockIdx.x;
    const int n    = blockIdx.y;
    const int tid  = threadIdx.x;
    const int lane = tid & 31;
    const int wid  = tid >> 5;       // 0..11
    const int kk   = wid >> 2;       // k
    const int pbase = (wid & 3) * 32;

    const float* xb = x + ((size_t)n * C_ * T_ + t) * V_;
    for (int i = tid; i < C_ * V_; i += XA_THREADS) {
        int ci = i / V_;
        int v  = i - ci * V_;
        xsp[((ci >> 1) * V_ + v) * 2 + (ci & 1)] = xb[(size_t)ci * (T_ * V_) + v];
    }
    for (int i = tid; i < K_ * V_ * V_; i += XA_THREADS)
        ams[i] = A[i] * Mm[i];
    __syncthreads();

    const int w = (lane < V_) ? lane : (V_ - 1);

    // AM row for (kk, :, w) packed as (am, am)
    uint64_t amr[V_];
    #pragma unroll
    for (int v = 0; v < V_; ++v) {
        float a = ams[(kk * V_ + v) * V_ + w];
        asm("mov.b64 %0, {%1, %1};" : "=l"(amr[v]) : "f"(a));
    }

    #pragma unroll 4
    for (int pp = 0; pp < 32; ++pp) {
        const int p = pbase + pp;
        const uint64_t* xv = (const uint64_t*)(xsp + p * (V_ * 2));
        uint64_t s2 = 0ull;   // (0.f, 0.f)
        #pragma unroll
        for (int v = 0; v < V_; ++v) {
            uint64_t xp = xv[v];
            asm("fma.rn.f32x2 %0, %1, %2, %0;" : "+l"(s2) : "l"(xp), "l"(amr[v]));
        }
        uint32_t lo, hi;
        asm("mov.b64 {%0, %1}, %2;" : "=r"(lo), "=r"(hi) : "l"(s2));
        __half2 h = __floats2half2_rn(__uint_as_float(lo), __uint_as_float(hi));
        if (lane < V_)
            *(__half2*)(hout + w * HSTRIDE + kk * C_ + p * 2) = h;
    }
    __syncthreads();

    // coalesced writeout: 25 rows x 768 halfs
    __half* outb = xa_buf + ((size_t)n * J_ + (size_t)t * V_) * KD1;
    for (int i = tid; i < (V_ * KD1) / 8; i += XA_THREADS) {   // 2400 uint4
        int w2 = i / 96;
        int c8 = i - w2 * 96;
        uint4 vv = *(const uint4*)(hout + w2 * HSTRIDE + c8 * 8);
        *(uint4*)(outb + (size_t)w2 * KD1 + c8 * 8) = vv;
    }
}

// ---------------------------------------------------------------------------
// GEMM1: sgc = Wa @ xa  -> BN1+ReLU+bcw -> gt[n][j][c] fp16 (unchanged)
// ---------------------------------------------------------------------------
#define G_STAGE 32768
#define G_SMEM  98304
#define IT1 12

__global__ void __launch_bounds__(256, 2) gemm1_kernel(
    const float* __restrict__ g1, const float* __restrict__ b1,
    const float* __restrict__ m1, const float* __restrict__ v1)
{
    extern __shared__ char smraw[];
    const uint32_t sb = smem_u32(smraw);
    const int tid  = threadIdx.x;
    const int wid  = tid >> 5;
    const int lane = tid & 31;
    const int j0   = blockIdx.x * 128;
    const int co0  = blockIdx.y * 128;
    const int n    = blockIdx.z;
    const int cw = (wid & 3) * 32;
    const int jw = (wid >> 2) * 64;

    const __half* xan = xa_buf + (size_t)n * J_ * KD1;

    float acc[2][8][4];
    #pragma unroll
    for (int mi = 0; mi < 2; ++mi)
        #pragma unroll
        for (int nf = 0; nf < 8; ++nf)
            #pragma unroll
            for (int q = 0; q < 4; ++q) acc[mi][nf][q] = 0.f;

    auto load_stage = [&](int it, int slot) {
        const uint32_t base = sb + (uint32_t)slot * G_STAGE;
        const int kb = it * 64;
        #pragma unroll
        for (int q = 0; q < 4; ++q) {
            const int c   = tid + q * 256;
            const int row = c >> 3;
            const int ch  = c & 7;
            const uint32_t sw = (uint32_t)((ch ^ (row & 7)) << 4);
            const __half* as = wa_buf + (size_t)(co0 + row) * KD1 + kb + ch * 8;
            cpa16(base + row * 128 + sw, as, 16);
            const int jp = j0 + row;
            const bool v = jp < J_;
            const __half* bs = xan + (size_t)(v ? jp : 0) * KD1 + kb + ch * 8;
            cpa16(base + 16384 + row * 128 + sw, bs, v ? 16 : 0);
        }
        cpa_commit();
    };

    load_stage(0, 0);
    load_stage(1, 1);

    const int rs  = lane & 7;
    const int hiA = lane >> 4;
    const int hiB = (lane >> 3) & 1;
    uint32_t rowA[2], rowB[4];
    #pragma unroll
    for (int mi = 0; mi < 2; ++mi)
        rowA[mi] = (uint32_t)((cw + mi * 16 + (lane & 15)) * 128);
    #pragma unroll
    for (int nb = 0; nb < 4; ++nb)
        rowB[nb] = (uint32_t)((jw + nb * 16 + (lane & 7) + (((lane >> 4) & 1) << 3)) * 128 + 16384);

    int wslot = 2, cslot = 0;
    for (int it = 0; it < IT1; ++it) {
        if (it < IT1 - 1) cpa_wait<1>(); else cpa_wait<0>();
        __syncthreads();
        if (it + 2 < IT1) {
            load_stage(it + 2, wslot);
            wslot = (wslot == 2) ? 0 : wslot + 1;
        }
        const uint32_t base = sb + (uint32_t)cslot * G_STAGE;
        cslot = (cslot == 2) ? 0 : cslot + 1;
        #pragma unroll
        for (int ks = 0; ks < 4; ++ks) {
            uint32_t aa[2][4], bb[4][4];
            #pragma unroll
            for (int mi = 0; mi < 2; ++mi)
                ldsm4(aa[mi], base + rowA[mi] + (uint32_t)((((ks * 2 + hiA) ^ rs)) << 4));
            #pragma unroll
            for (int nb = 0; nb < 4; ++nb)
                ldsm4(bb[nb], base + rowB[nb] + (uint32_t)((((ks * 2 + hiB) ^ rs)) << 4));
            #pragma unroll
            for (int mi = 0; mi < 2; ++mi)
                #pragma unroll
                for (int nf = 0; nf < 8; ++nf) {
                    const int nb = nf >> 1;
                    if (nf & 1) mma16816(acc[mi][nf], aa[mi], bb[nb][2], bb[nb][3]);
                    else        mma16816(acc[mi][nf], aa[mi], bb[nb][0], bb[nb][1]);
                }
        }
    }
    __syncthreads();

    // epilogue: bcw + BN1 + ReLU -> smem transpose tile -> gt
    __half* ts = (__half*)smraw;   // [128][136]
    #pragma unroll
    for (int mi = 0; mi < 2; ++mi) {
        #pragma unroll
        for (int hh = 0; hh < 2; ++hh) {
            const int col = cw + mi * 16 + (lane >> 2) + hh * 8;
            const int cog = co0 + col;
            const float scl = g1[cog] * rsqrtf(v1[cog] + BN_EPS);
            const float shf = b1[cog] - m1[cog] * scl;
            const float* bcr = bcw_buf + cog * V_;
            #pragma unroll
            for (int nf = 0; nf < 8; ++nf) {
                const int jl = jw + nf * 8 + (lane & 3) * 2;
                const int jg = j0 + jl;
                const int w0 = jg % 25;
                const int w1 = (w0 == 24) ? 0 : w0 + 1;
                float r0 = acc[mi][nf][hh * 2 + 0] + bcr[w0];
                float r1 = acc[mi][nf][hh * 2 + 1] + bcr[w1];
                r0 = fmaf(r0, scl, shf);
                r1 = fmaf(r1, scl, shf);
                r0 = r0 > 0.f ? r0 : 0.f;
                r1 = r1 > 0.f ? r1 : 0.f;
                ts[jl * 136 + col]       = __float2half_rn(r0);
                ts[(jl + 1) * 136 + col] = __float2half_rn(r1);
            }
        }
    }
    __syncthreads();

    __half* gout = gt_buf + (size_t)n * J_ * C_;
    #pragma unroll
    for (int p = 0; p < 8; ++p) {
        const int idx = p * 256 + tid;
        const int cc = idx & 15;
        const int j  = idx >> 4;
        const int jg = j0 + j;
        if (jg < J_) {
            uint4 vv = *(const uint4*)(ts + j * 136 + cc * 8);
            *(uint4*)(gout + (size_t)jg * C_ + co0 + cc * 8) = vv;
        }
    }
}

// ---------------------------------------------------------------------------
// GEMM2 v2: temporal conv + BN2 + ReLU + residual
// B superset (328 gt rows x 64 ci) loaded once per ci-chunk; 9 dt reuse it
// with row offset 25*dt. A (wt2) double-buffered 16KB tiles.
// ---------------------------------------------------------------------------
#define B2_ROWS 328
#define B2_BYTES (B2_ROWS * 128)      // 41984
#define A2_BYTES 16384
#define SM2_TOTAL (B2_BYTES + 2 * A2_BYTES)   // 74752

__global__ void __launch_bounds__(256, 2) gemm2_kernel(
    const float* __restrict__ x, const float* __restrict__ tcb,
    const float* __restrict__ g2, const float* __restrict__ b2,
    const float* __restrict__ m2, const float* __restrict__ v2,
    float* __restrict__ out)
{
    extern __shared__ char smraw2[];
    const uint32_t sb = smem_u32(smraw2);
    const int tid  = threadIdx.x;
    const int wid  = tid >> 5;
    const int lane = tid & 31;
    const int j0   = blockIdx.x * 128;
    const int co0  = blockIdx.y * 128;
    const int n    = blockIdx.z;
    const int cw = (wid & 3) * 32;
    const int jw = (wid >> 2) * 64;

    const __half* gtn = gt_buf + (size_t)n * J_ * C_;

    float acc[2][8][4];
    #pragma unroll
    for (int mi = 0; mi < 2; ++mi)
        #pragma unroll
        for (int nf = 0; nf < 8; ++nf)
            #pragma unroll
            for (int q = 0; q < 4; ++q) acc[mi][nf][q] = 0.f;

    auto load_B = [&](int chunk) {
        const int cic = chunk << 6;
        for (int i = tid; i < B2_ROWS * 8; i += 256) {
            const int row = i >> 3;
            const int ch  = i & 7;
            const int jp  = j0 - 100 + row;
            const bool v  = (jp >= 0) && (jp < J_);
            const __half* bs = gtn + (size_t)(v ? jp : 0) * C_ + cic + ch * 8;
            cpa16(sb + row * 128 + (uint32_t)((ch ^ (row & 7)) << 4), bs, v ? 16 : 0);
        }
    };
    auto load_A = [&](int dt, int chunk, int slot) {
        const int cic = chunk << 6;
        const uint32_t base = sb + B2_BYTES + (uint32_t)slot * A2_BYTES;
        #pragma unroll
        for (int q = 0; q < 4; ++q) {
            const int c   = tid + q * 256;
            const int row = c >> 3;
            const int ch  = c & 7;
            const __half* as = wt2_buf + (size_t)dt * (C_ * C_) +
                               (size_t)(co0 + row) * C_ + cic + ch * 8;
            cpa16(base + row * 128 + (uint32_t)((ch ^ (row & 7)) << 4), as, 16);
        }
    };

    // frag base offsets
    const int hiA = lane >> 4;
    const int hiB = (lane >> 3) & 1;
    const int rsA = lane & 7;
    uint32_t rowA[2], rowB[4];
    #pragma unroll
    for (int mi = 0; mi < 2; ++mi)
        rowA[mi] = (uint32_t)((cw + mi * 16 + (lane & 15)) * 128);
    #pragma unroll
    for (int nb = 0; nb < 4; ++nb)
        rowB[nb] = (uint32_t)((jw + nb * 16 + (lane & 7) + (((lane >> 4) & 1) << 3)) * 128);

    // prologue
    load_B(0);
    load_A(0, 0, 0);
    cpa_commit();
    cpa_wait<0>();
    __syncthreads();

    int cur = 0;
    for (int it = 0; it < 36; ++it) {
        const int dt    = it % TK_;
        const int chunk = it / TK_;

        if (it + 1 < 36) {
            const int nit = it + 1;
            load_A(nit % TK_, nit / TK_, cur ^ 1);
            cpa_commit();
        }

        // MMA for (chunk, dt): B rows shifted by 25*dt within superset
        {
            const uint32_t abase = sb + B2_BYTES + (uint32_t)cur * A2_BYTES;
            const uint32_t boff  = (uint32_t)(dt * 25 * 128);
            const int rsB = ((lane & 7) + dt) & 7;
            #pragma unroll
            for (int ks = 0; ks < 4; ++ks) {
                uint32_t aa[2][4], bb[4][4];
                #pragma unroll
                for (int mi = 0; mi < 2; ++mi)
                    ldsm4(aa[mi], abase + rowA[mi] + (uint32_t)((((ks * 2 + hiA) ^ rsA)) << 4));
                #pragma unroll
                for (int nb = 0; nb < 4; ++nb)
                    ldsm4(bb[nb], sb + rowB[nb] + boff + (uint32_t)((((ks * 2 + hiB) ^ rsB)) << 4));
                #pragma unroll
                for (int mi = 0; mi < 2; ++mi)
                    #pragma unroll
                    for (int nf = 0; nf < 8; ++nf) {
                        const int nb = nf >> 1;
                        if (nf & 1) mma16816(acc[mi][nf], aa[mi], bb[nb][2], bb[nb][3]);
                        else        mma16816(acc[mi][nf], aa[mi], bb[nb][0], bb[nb][1]);
                    }
            }
        }

        if (dt == TK_ - 1 && chunk < 3) {
            cpa_wait<0>();
            __syncthreads();          // all warps done with current B
            load_B(chunk + 1);
            cpa_commit();
            cpa_wait<0>();
            __syncthreads();          // new B visible
        } else {
            cpa_wait<0>();
            __syncthreads();
        }
        cur ^= 1;
    }

    // epilogue: BN2 + ReLU + residual
    #pragma unroll
    for (int mi = 0; mi < 2; ++mi) {
        #pragma unroll
        for (int hh = 0; hh < 2; ++hh) {
            const int co = co0 + cw + mi * 16 + (lane >> 2) + hh * 8;
            const float scl = g2[co] * rsqrtf(v2[co] + BN_EPS);
            const float shf = b2[co] - m2[co] * scl + tcb[co] * scl;
            const float* xr = x   + (size_t)(n * C_ + co) * J_;
            float* orow     = out + (size_t)(n * C_ + co) * J_;
            #pragma unroll
            for (int nf = 0; nf < 8; ++nf) {
                const int jj = j0 + jw + nf * 8 + (lane & 3) * 2;
                if (jj < J_) {
                    float v0 = fmaf(acc[mi][nf][hh * 2 + 0], scl, shf);
                    float v1 = fmaf(acc[mi][nf][hh * 2 + 1], scl, shf);
                    v0 = v0 > 0.f ? v0 : 0.f;
                    v1 = v1 > 0.f ? v1 : 0.f;
                    float2 xv = *(const float2*)(xr + jj);
                    float2 o;
                    o.x = v0 + xv.x;
                    o.y = v1 + xv.y;
                    *(float2*)(orow + jj) = o;
                }
            }
        }
    }
}

// ---------------------------------------------------------------------------
extern "C" void kernel_launch(void* const* d_in, const int* in_sizes, int n_in,
                              void* d_out, int out_size)
{
    const float* x   = (const float*)d_in[0];
    const float* A   = (const float*)d_in[1];
    // d_in[2] = att_A (unused)
    const float* Mm  = (const float*)d_in[3];
    const float* W   = (const float*)d_in[4];
    const float* cb  = (const float*)d_in[5];
    const float* g1  = (const float*)d_in[6];
    const float* b1  = (const float*)d_in[7];
    const float* m1  = (const float*)d_in[8];
    const float* v1  = (const float*)d_in[9];
    const float* tw  = (const float*)d_in[10];
    const float* tcb = (const float*)d_in[11];
    const float* g2  = (const float*)d_in[12];
    const float* b2  = (const float*)d_in[13];
    const float* m2  = (const float*)d_in[14];
    const float* v2  = (const float*)d_in[15];
    float* out = (float*)d_out;

    cudaFuncSetAttribute(xa_kernel,    cudaFuncAttributeMaxDynamicSharedMemorySize, XA_SMEM);
    cudaFuncSetAttribute(gemm1_kernel, cudaFuncAttributeMaxDynamicSharedMemorySize, G_SMEM);
    cudaFuncSetAttribute(gemm2_kernel, cudaFuncAttributeMaxDynamicSharedMemorySize, SM2_TOTAL);

    // prep
    wt2_kernel<<<(TK_ * C_ * C_ + 255) / 256, 256>>>(tw);
    wa_kernel<<<(C_ * KD1 + 255) / 256, 256>>>(W);
    bcw_kernel<<<1, 256>>>(A, Mm, cb);

    // xa: graph-contracted input
    dim3 gxa(T_, N_);
    xa_kernel<<<gxa, XA_THREADS, XA_SMEM>>>(x, A, Mm);

    // GEMM1: S_GC + BN1 + ReLU -> gt
    dim3 gg1((J_ + 127) / 128, C_ / 128, N_);
    gemm1_kernel<<<gg1, 256, G_SMEM>>>(g1, b1, m1, v1);

    // GEMM2: temporal conv + BN2 + ReLU + residual
    dim3 gg2((J_ + 127) / 128, C_ / 128, N_);
    gemm2_kernel<<<gg2, 256, SM2_TOTAL>>>(x, tcb, g2, b2, m2, v2, out);
}

// round 7
// speedup vs baseline: 1.1110x; 1.1110x over previous
#include <cuda_runtime.h>
#include <cuda_fp16.h>
#include <cstdint>

#define N_ 16
#define C_ 256
#define T_ 300
#define V_ 25
#define K_ 3
#define TK_ 9
#define J_ 7500
#define KD1 768            // GEMM1 K-dim (k,ci)
#define BN_EPS 1e-5f

// static device scratch
__device__ __align__(256) __half xa_buf[(size_t)N_ * J_ * KD1];   // 184 MB
__device__ __align__(256) __half gt_buf[(size_t)N_ * J_ * C_];    // 61.4 MB
__device__ __align__(256) __half wt2_buf[TK_ * C_ * C_];          // [dt][co][ci]
__device__ __align__(256) __half wa_buf[C_ * KD1];                // [co][(k,ci)]
__device__ __align__(256) __half amh_buf[80 * 32];                // [kw-row][v] fp16
__device__ float bcw_buf[C_ * V_];                                // bias*sum(AM)

// ---------------------------------------------------------------------------
// PTX helpers
// ---------------------------------------------------------------------------
__device__ __forceinline__ uint32_t smem_u32(const void* p) {
    uint32_t a;
    asm("{ .reg .u64 t; cvta.to.shared.u64 t, %1; cvt.u32.u64 %0, t; }" : "=r"(a) : "l"(p));
    return a;
}
__device__ __forceinline__ void ldsm4(uint32_t* r, uint32_t addr) {
    asm volatile("ldmatrix.sync.aligned.m8n8.x4.shared.b16 {%0,%1,%2,%3}, [%4];"
                 : "=r"(r[0]), "=r"(r[1]), "=r"(r[2]), "=r"(r[3]) : "r"(addr));
}
__device__ __forceinline__ void mma16816(float* c, const uint32_t* a,
                                         uint32_t b0, uint32_t b1) {
    asm volatile(
        "mma.sync.aligned.m16n8k16.row.col.f32.f16.f16.f32 "
        "{%0,%1,%2,%3}, {%4,%5,%6,%7}, {%8,%9}, {%0,%1,%2,%3};"
        : "+f"(c[0]), "+f"(c[1]), "+f"(c[2]), "+f"(c[3])
        : "r"(a[0]), "r"(a[1]), "r"(a[2]), "r"(a[3]), "r"(b0), "r"(b1));
}
__device__ __forceinline__ void cpa16(uint32_t dst, const void* src, int srcsize) {
    asm volatile("cp.async.cg.shared.global [%0], [%1], 16, %2;"
                 :: "r"(dst), "l"(src), "r"(srcsize));
}
__device__ __forceinline__ void cpa_commit() {
    asm volatile("cp.async.commit_group;" ::: "memory");
}
template <int NN>
__device__ __forceinline__ void cpa_wait() {
    asm volatile("cp.async.wait_group %0;" :: "n"(NN) : "memory");
}

// ---------------------------------------------------------------------------
// prep kernels
// ---------------------------------------------------------------------------
__global__ void wt2_kernel(const float* __restrict__ tw) {
    int i = blockIdx.x * 256 + threadIdx.x;
    if (i < TK_ * C_ * C_) {
        int dt = i / (C_ * C_);
        int r  = i - dt * C_ * C_;
        int co = r >> 8;
        int ci = r & 255;
        wt2_buf[i] = __float2half_rn(tw[(co * C_ + ci) * TK_ + dt]);
    }
}

__global__ void wa_kernel(const float* __restrict__ cw) {
    int i = blockIdx.x * 256 + threadIdx.x;
    if (i < C_ * KD1) {
        int co = i / KD1;
        int kk = i - co * KD1;
        int k  = kk >> 8;
        int ci = kk & 255;
        wa_buf[i] = __float2half_rn(cw[(k * C_ + co) * C_ + ci]);
    }
}

__global__ void amh_kernel(const float* __restrict__ A, const float* __restrict__ Mm) {
    int i = blockIdx.x * 256 + threadIdx.x;
    if (i < 80 * 32) {
        int r = i >> 5;
        int v = i & 31;
        float val = 0.f;
        if (r < 75 && v < V_) {
            int k = r / V_;
            int w = r - k * V_;
            int idx = (k * V_ + v) * V_ + w;
            val = A[idx] * Mm[idx];
        }
        amh_buf[i] = __float2half_rn(val);
    }
}

__global__ void bcw_kernel(const float* __restrict__ A, const float* __restrict__ Mm,
                           const float* __restrict__ bias) {
    __shared__ float S[K_ * V_];
    int tid = threadIdx.x;
    if (tid < K_ * V_) {
        int k = tid / V_;
        int w = tid - k * V_;
        float s = 0.f;
        for (int v = 0; v < V_; ++v) {
            int idx = (k * V_ + v) * V_ + w;
            s += A[idx] * Mm[idx];
        }
        S[tid] = s;
    }
    __syncthreads();
    int c = tid;   // 256 threads
    for (int w = 0; w < V_; ++w) {
        float s = 0.f;
        #pragma unroll
        for (int k = 0; k < K_; ++k)
            s += bias[k * C_ + c] * S[k * V_ + w];
        bcw_buf[c * V_ + w] = s;
    }
}

// ---------------------------------------------------------------------------
// xa via MMA: per (n,t): D[(k,w)=75][ci=256] = AMh[75x32] . xB[256x32]^T
// 320 threads = 10 warps (5 m-slices x 2 n-halves). K=25 padded to 32.
// output transposed through smem -> xa[j=(t,w)][(k,ci)] coalesced rows.
// x rows start at byte offset t*100 (NOT 16B aligned): scalar loads only.
// ---------------------------------------------------------------------------
#define XAT 320
#define XB_ROWB 80                  // smem row stride bytes (32 halfs + pad)
#define XA_A_OFF 20480              // xB: 256*80 = 20480
#define DST_STRIDE 264              // halfs
#define XA_SMEM2 42240              // max(20480+6400, 80*264*2)

__global__ void __launch_bounds__(XAT) xa_mma_kernel(const float* __restrict__ x)
{
    extern __shared__ char sxm[];
    const uint32_t sb = smem_u32(sxm);
    const int tid  = threadIdx.x;
    const int lane = tid & 31;
    const int wid  = tid >> 5;       // 0..9
    const int s    = wid >> 1;       // m-slice 0..4
    const int h    = wid & 1;        // n-half 0..1
    const int t    = blockIdx.x;
    const int n    = blockIdx.y;

    // load A tile (80 rows x 64B) -> smem, stride 80B (amh_buf is 16B aligned)
    {
        uint4 v = ((const uint4*)amh_buf)[tid];
        *(uint4*)(sxm + XA_A_OFF + (tid >> 2) * XB_ROWB + (tid & 3) * 16) = v;
    }
    // load x slice -> xB fp16 (256 rows x 32 halfs, v>=25 zero); SCALAR float
    // loads (row base = t*100 bytes, unaligned for float4), __half2 stores.
    const float* xb = x + ((size_t)n * C_ * T_ + t) * V_;
    for (int idx = tid; idx < 256 * 16; idx += XAT) {
        const int row = idx >> 4;
        const int p   = idx & 15;          // half2 slot (2 halfs each)
        __half2 h2;
        if (p < 12) {
            const float* rp = xb + (size_t)row * (T_ * V_) + p * 2;
            h2 = __floats2half2_rn(rp[0], rp[1]);
        } else if (p == 12) {
            h2 = __floats2half2_rn(xb[(size_t)row * (T_ * V_) + 24], 0.f);
        } else {
            h2 = __floats2half2_rn(0.f, 0.f);
        }
        *(__half2*)(sxm + row * XB_ROWB + p * 4) = h2;
    }
    __syncthreads();

    // A fragments (once)
    uint32_t aa[2][4];
    {
        const uint32_t abase = sb + XA_A_OFF + (uint32_t)((s * 16 + (lane & 15)) * XB_ROWB)
                               + (uint32_t)((lane >> 4) << 4);
        ldsm4(aa[0], abase);        // k 0..15
        ldsm4(aa[1], abase + 32);   // k 16..31
    }

    float acc[16][4];
    #pragma unroll
    for (int nf = 0; nf < 16; ++nf)
        #pragma unroll
        for (int q = 0; q < 4; ++q) acc[nf][q] = 0.f;

    const uint32_t brow0 = sb + (uint32_t)((h * 128 + (lane & 7) + (((lane >> 4) & 1) << 3)) * XB_ROWB)
                           + (uint32_t)(((lane >> 3) & 1) << 4);
    #pragma unroll
    for (int ks = 0; ks < 2; ++ks) {
        #pragma unroll
        for (int nb = 0; nb < 8; ++nb) {
            uint32_t bb[4];
            ldsm4(bb, brow0 + (uint32_t)(nb * 16 * XB_ROWB) + (uint32_t)(ks * 32));
            mma16816(acc[nb * 2 + 0], aa[ks], bb[0], bb[1]);
            mma16816(acc[nb * 2 + 1], aa[ks], bb[2], bb[3]);
        }
    }
    __syncthreads();

    // stage D -> smem fp16 [80][DST_STRIDE]
    __half* Dst = (__half*)sxm;
    #pragma unroll
    for (int nf = 0; nf < 16; ++nf) {
        #pragma unroll
        for (int hh = 0; hh < 2; ++hh) {
            const int row = s * 16 + (lane >> 2) + hh * 8;
            const int col = h * 128 + nf * 8 + (lane & 3) * 2;
            __half2 p = __floats2half2_rn(acc[nf][hh * 2 + 0], acc[nf][hh * 2 + 1]);
            *(__half2*)(Dst + row * DST_STRIDE + col) = p;
        }
    }
    __syncthreads();

    // writeout: 75 rows x 256 halfs -> xa[t*25+w][k*256 .. +256]
    __half* outb = xa_buf + ((size_t)n * J_ + (size_t)t * V_) * KD1;
    for (int i = tid; i < 75 * 32; i += XAT) {
        const int r = i >> 5;       // kw row
        const int q = i & 31;       // uint4 index within 256 halfs
        const int k = r / V_;
        const int w = r - k * V_;
        uint4 v = *(const uint4*)(Dst + r * DST_STRIDE + q * 8);
        *(uint4*)(outb + (size_t)w * KD1 + k * C_ + q * 8) = v;
    }
}

// ---------------------------------------------------------------------------
// GEMM1: sgc = Wa @ xa  -> BN1+ReLU+bcw -> gt[n][j][c] fp16
// ---------------------------------------------------------------------------
#define G_STAGE 32768
#define G_SMEM  98304
#define IT1 12

__global__ void __launch_bounds__(256, 2) gemm1_kernel(
    const float* __restrict__ g1, const float* __restrict__ b1,
    const float* __restrict__ m1, const float* __restrict__ v1)
{
    extern __shared__ char smraw[];
    const uint32_t sb = smem_u32(smraw);
    const int tid  = threadIdx.x;
    const int wid  = tid >> 5;
    const int lane = tid & 31;
    const int j0   = blockIdx.x * 128;
    const int co0  = blockIdx.y * 128;
    const int n    = blockIdx.z;
    const int cw = (wid & 3) * 32;
    const int jw = (wid >> 2) * 64;

    const __half* xan = xa_buf + (size_t)n * J_ * KD1;

    float acc[2][8][4];
    #pragma unroll
    for (int mi = 0; mi < 2; ++mi)
        #pragma unroll
        for (int nf = 0; nf < 8; ++nf)
            #pragma unroll
            for (int q = 0; q < 4; ++q) acc[mi][nf][q] = 0.f;

    auto load_stage = [&](int it, int slot) {
        const uint32_t base = sb + (uint32_t)slot * G_STAGE;
        const int kb = it * 64;
        #pragma unroll
        for (int q = 0; q < 4; ++q) {
            const int c   = tid + q * 256;
            const int row = c >> 3;
            const int ch  = c & 7;
            const uint32_t sw = (uint32_t)((ch ^ (row & 7)) << 4);
            const __half* as = wa_buf + (size_t)(co0 + row) * KD1 + kb + ch * 8;
            cpa16(base + row * 128 + sw, as, 16);
            const int jp = j0 + row;
            const bool v = jp < J_;
            const __half* bs = xan + (size_t)(v ? jp : 0) * KD1 + kb + ch * 8;
            cpa16(base + 16384 + row * 128 + sw, bs, v ? 16 : 0);
        }
        cpa_commit();
    };

    load_stage(0, 0);
    load_stage(1, 1);

    const int rs  = lane & 7;
    const int hiA = lane >> 4;
    const int hiB = (lane >> 3) & 1;
    uint32_t rowA[2], rowB[4];
    #pragma unroll
    for (int mi = 0; mi < 2; ++mi)
        rowA[mi] = (uint32_t)((cw + mi * 16 + (lane & 15)) * 128);
    #pragma unroll
    for (int nb = 0; nb < 4; ++nb)
        rowB[nb] = (uint32_t)((jw + nb * 16 + (lane & 7) + (((lane >> 4) & 1) << 3)) * 128 + 16384);

    int wslot = 2, cslot = 0;
    for (int it = 0; it < IT1; ++it) {
        if (it < IT1 - 1) cpa_wait<1>(); else cpa_wait<0>();
        __syncthreads();
        if (it + 2 < IT1) {
            load_stage(it + 2, wslot);
            wslot = (wslot == 2) ? 0 : wslot + 1;
        }
        const uint32_t base = sb + (uint32_t)cslot * G_STAGE;
        cslot = (cslot == 2) ? 0 : cslot + 1;
        #pragma unroll
        for (int ks = 0; ks < 4; ++ks) {
            uint32_t aa[2][4], bb[4][4];
            #pragma unroll
            for (int mi = 0; mi < 2; ++mi)
                ldsm4(aa[mi], base + rowA[mi] + (uint32_t)((((ks * 2 + hiA) ^ rs)) << 4));
            #pragma unroll
            for (int nb = 0; nb < 4; ++nb)
                ldsm4(bb[nb], base + rowB[nb] + (uint32_t)((((ks * 2 + hiB) ^ rs)) << 4));
            #pragma unroll
            for (int mi = 0; mi < 2; ++mi)
                #pragma unroll
                for (int nf = 0; nf < 8; ++nf) {
                    const int nb = nf >> 1;
                    if (nf & 1) mma16816(acc[mi][nf], aa[mi], bb[nb][2], bb[nb][3]);
                    else        mma16816(acc[mi][nf], aa[mi], bb[nb][0], bb[nb][1]);
                }
        }
    }
    __syncthreads();

    // epilogue: bcw + BN1 + ReLU -> smem transpose tile -> gt
    __half* ts = (__half*)smraw;   // [128][136]
    #pragma unroll
    for (int mi = 0; mi < 2; ++mi) {
        #pragma unroll
        for (int hh = 0; hh < 2; ++hh) {
            const int col = cw + mi * 16 + (lane >> 2) + hh * 8;
            const int cog = co0 + col;
            const float scl = g1[cog] * rsqrtf(v1[cog] + BN_EPS);
            const float shf = b1[cog] - m1[cog] * scl;
            const float* bcr = bcw_buf + cog * V_;
            #pragma unroll
            for (int nf = 0; nf < 8; ++nf) {
                const int jl = jw + nf * 8 + (lane & 3) * 2;
                const int jg = j0 + jl;
                const int w0 = jg % 25;
                const int w1 = (w0 == 24) ? 0 : w0 + 1;
                float r0 = acc[mi][nf][hh * 2 + 0] + bcr[w0];
                float r1 = acc[mi][nf][hh * 2 + 1] + bcr[w1];
                r0 = fmaf(r0, scl, shf);
                r1 = fmaf(r1, scl, shf);
                r0 = r0 > 0.f ? r0 : 0.f;
                r1 = r1 > 0.f ? r1 : 0.f;
                ts[jl * 136 + col]       = __float2half_rn(r0);
                ts[(jl + 1) * 136 + col] = __float2half_rn(r1);
            }
        }
    }
    __syncthreads();

    __half* gout = gt_buf + (size_t)n * J_ * C_;
    #pragma unroll
    for (int p = 0; p < 8; ++p) {
        const int idx = p * 256 + tid;
        const int cc = idx & 15;
        const int j  = idx >> 4;
        const int jg = j0 + j;
        if (jg < J_) {
            uint4 vv = *(const uint4*)(ts + j * 136 + cc * 8);
            *(uint4*)(gout + (size_t)jg * C_ + co0 + cc * 8) = vv;
        }
    }
}

// ---------------------------------------------------------------------------
// GEMM2 (round-4 proven version): temporal conv + BN2 + ReLU + residual
// ---------------------------------------------------------------------------
#define IT2 36

__global__ void __launch_bounds__(256, 2) gemm2_kernel(
    const float* __restrict__ x, const float* __restrict__ tcb,
    const float* __restrict__ g2, const float* __restrict__ b2,
    const float* __restrict__ m2, const float* __restrict__ v2,
    float* __restrict__ out)
{
    extern __shared__ char smraw2[];
    const uint32_t sb = smem_u32(smraw2);
    const int tid  = threadIdx.x;
    const int wid  = tid >> 5;
    const int lane = tid & 31;
    const int j0   = blockIdx.x * 128;
    const int co0  = blockIdx.y * 128;
    const int n    = blockIdx.z;
    const int cw = (wid & 3) * 32;
    const int jw = (wid >> 2) * 64;

    const __half* gtn = gt_buf + (size_t)n * J_ * C_;

    float acc[2][8][4];
    #pragma unroll
    for (int mi = 0; mi < 2; ++mi)
        #pragma unroll
        for (int nf = 0; nf < 8; ++nf)
            #pragma unroll
            for (int q = 0; q < 4; ++q) acc[mi][nf][q] = 0.f;

    auto load_stage = [&](int it, int slot) {
        const uint32_t base = sb + (uint32_t)slot * G_STAGE;
        const int dt  = it >> 2;
        const int cic = (it & 3) << 6;
        const int s   = (dt - (TK_ - 1) / 2) * V_;
        #pragma unroll
        for (int q = 0; q < 4; ++q) {
            const int c   = tid + q * 256;
            const int row = c >> 3;
            const int ch  = c & 7;
            const uint32_t sw = (uint32_t)((ch ^ (row & 7)) << 4);
            const __half* as = wt2_buf + (size_t)dt * (C_ * C_) +
                               (size_t)(co0 + row) * C_ + cic + ch * 8;
            cpa16(base + row * 128 + sw, as, 16);
            const int jp = j0 + row + s;
            const bool v = (jp >= 0) && (jp < J_);
            const __half* bs = gtn + (size_t)(v ? jp : 0) * C_ + cic + ch * 8;
            cpa16(base + 16384 + row * 128 + sw, bs, v ? 16 : 0);
        }
        cpa_commit();
    };

    load_stage(0, 0);
    load_stage(1, 1);

    const int rs  = lane & 7;
    const int hiA = lane >> 4;
    const int hiB = (lane >> 3) & 1;
    uint32_t rowA[2], rowB[4];
    #pragma unroll
    for (int mi = 0; mi < 2; ++mi)
        rowA[mi] = (uint32_t)((cw + mi * 16 + (lane & 15)) * 128);
    #pragma unroll
    for (int nb = 0; nb < 4; ++nb)
        rowB[nb] = (uint32_t)((jw + nb * 16 + (lane & 7) + (((lane >> 4) & 1) << 3)) * 128 + 16384);

    int wslot = 2, cslot = 0;
    for (int it = 0; it < IT2; ++it) {
        if (it < IT2 - 1) cpa_wait<1>(); else cpa_wait<0>();
        __syncthreads();
        if (it + 2 < IT2) {
            load_stage(it + 2, wslot);
            wslot = (wslot == 2) ? 0 : wslot + 1;
        }
        const uint32_t base = sb + (uint32_t)cslot * G_STAGE;
        cslot = (cslot == 2) ? 0 : cslot + 1;
        #pragma unroll
        for (int ks = 0; ks < 4; ++ks) {
            uint32_t aa[2][4], bb[4][4];
            #pragma unroll
            for (int mi = 0; mi < 2; ++mi)
                ldsm4(aa[mi], base + rowA[mi] + (uint32_t)((((ks * 2 + hiA) ^ rs)) << 4));
            #pragma unroll
            for (int nb = 0; nb < 4; ++nb)
                ldsm4(bb[nb], base + rowB[nb] + (uint32_t)((((ks * 2 + hiB) ^ rs)) << 4));
            #pragma unroll
            for (int mi = 0; mi < 2; ++mi)
                #pragma unroll
                for (int nf = 0; nf < 8; ++nf) {
                    const int nb = nf >> 1;
                    if (nf & 1) mma16816(acc[mi][nf], aa[mi], bb[nb][2], bb[nb][3]);
                    else        mma16816(acc[mi][nf], aa[mi], bb[nb][0], bb[nb][1]);
                }
        }
    }

    // epilogue: BN2 + ReLU + residual
    #pragma unroll
    for (int mi = 0; mi < 2; ++mi) {
        #pragma unroll
        for (int hh = 0; hh < 2; ++hh) {
            const int co = co0 + cw + mi * 16 + (lane >> 2) + hh * 8;
            const float scl = g2[co] * rsqrtf(v2[co] + BN_EPS);
            const float shf = b2[co] - m2[co] * scl + tcb[co] * scl;
            const float* xr = x   + (size_t)(n * C_ + co) * J_;
            float* orow     = out + (size_t)(n * C_ + co) * J_;
            #pragma unroll
            for (int nf = 0; nf < 8; ++nf) {
                const int jj = j0 + jw + nf * 8 + (lane & 3) * 2;
                if (jj < J_) {
                    float v0 = fmaf(acc[mi][nf][hh * 2 + 0], scl, shf);
                    float v1 = fmaf(acc[mi][nf][hh * 2 + 1], scl, shf);
                    v0 = v0 > 0.f ? v0 : 0.f;
                    v1 = v1 > 0.f ? v1 : 0.f;
                    float2 xv = *(const float2*)(xr + jj);
                    float2 o;
                    o.x = v0 + xv.x;
                    o.y = v1 + xv.y;
                    *(float2*)(orow + jj) = o;
                }
            }
        }
    }
}

// ---------------------------------------------------------------------------
extern "C" void kernel_launch(void* const* d_in, const int* in_sizes, int n_in,
                              void* d_out, int out_size)
{
    const float* x   = (const float*)d_in[0];
    const float* A   = (const float*)d_in[1];
    // d_in[2] = att_A (unused)
    const float* Mm  = (const float*)d_in[3];
    const float* W   = (const float*)d_in[4];
    const float* cb  = (const float*)d_in[5];
    const float* g1  = (const float*)d_in[6];
    const float* b1  = (const float*)d_in[7];
    const float* m1  = (const float*)d_in[8];
    const float* v1  = (const float*)d_in[9];
    const float* tw  = (const float*)d_in[10];
    const float* tcb = (const float*)d_in[11];
    const float* g2  = (const float*)d_in[12];
    const float* b2  = (const float*)d_in[13];
    const float* m2  = (const float*)d_in[14];
    const float* v2  = (const float*)d_in[15];
    float* out = (float*)d_out;

    cudaFuncSetAttribute(xa_mma_kernel, cudaFuncAttributeMaxDynamicSharedMemorySize, XA_SMEM2);
    cudaFuncSetAttribute(gemm1_kernel,  cudaFuncAttributeMaxDynamicSharedMemorySize, G_SMEM);
    cudaFuncSetAttribute(gemm2_kernel,  cudaFuncAttributeMaxDynamicSharedMemorySize, G_SMEM);

    // prep
    wt2_kernel<<<(TK_ * C_ * C_ + 255) / 256, 256>>>(tw);
    wa_kernel<<<(C_ * KD1 + 255) / 256, 256>>>(W);
    amh_kernel<<<(80 * 32 + 255) / 256, 256>>>(A, Mm);
    bcw_kernel<<<1, 256>>>(A, Mm, cb);

    // xa via MMA
    dim3 gxa(T_, N_);
    xa_mma_kernel<<<gxa, XAT, XA_SMEM2>>>(x);

    // GEMM1: S_GC + BN1 + ReLU -> gt
    dim3 gg1((J_ + 127) / 128, C_ / 128, N_);
    gemm1_kernel<<<gg1, 256, G_SMEM>>>(g1, b1, m1, v1);

    // GEMM2: temporal conv + BN2 + ReLU + residual
    dim3 gg2((J_ + 127) / 128, C_ / 128, N_);
    gemm2_kernel<<<gg2, 256, G_SMEM>>>(x, tcb, g2, b2, m2, v2, out);
}

// round 8
// speedup vs baseline: 1.2343x; 1.1110x over previous
#include <cuda_runtime.h>
#include <cuda_fp16.h>
#include <cstdint>

#define N_ 16
#define C_ 256
#define T_ 300
#define V_ 25
#define K_ 3
#define TK_ 9
#define J_ 7500
#define KD1 768            // GEMM1 K-dim (k,ci)
#define BN_EPS 1e-5f

// static device scratch
__device__ __align__(256) __half xa_buf[(size_t)N_ * J_ * KD1];   // 184 MB
__device__ __align__(256) __half gt_buf[(size_t)N_ * J_ * C_];    // 61.4 MB
__device__ __align__(256) __half wt2_buf[TK_ * C_ * C_];          // [dt][co][ci]
__device__ __align__(256) __half wa_buf[C_ * KD1];                // [co][(k,ci)]
__device__ __align__(256) __half amh_buf[80 * 32];                // [kw-row][v] fp16
__device__ float bcw_buf[C_ * V_];                                // bias*sum(AM)

// ---------------------------------------------------------------------------
// PTX helpers
// ---------------------------------------------------------------------------
__device__ __forceinline__ uint32_t smem_u32(const void* p) {
    uint32_t a;
    asm("{ .reg .u64 t; cvta.to.shared.u64 t, %1; cvt.u32.u64 %0, t; }" : "=r"(a) : "l"(p));
    return a;
}
__device__ __forceinline__ void ldsm4(uint32_t* r, uint32_t addr) {
    asm volatile("ldmatrix.sync.aligned.m8n8.x4.shared.b16 {%0,%1,%2,%3}, [%4];"
                 : "=r"(r[0]), "=r"(r[1]), "=r"(r[2]), "=r"(r[3]) : "r"(addr));
}
__device__ __forceinline__ void mma16816(float* c, const uint32_t* a,
                                         uint32_t b0, uint32_t b1) {
    asm volatile(
        "mma.sync.aligned.m16n8k16.row.col.f32.f16.f16.f32 "
        "{%0,%1,%2,%3}, {%4,%5,%6,%7}, {%8,%9}, {%0,%1,%2,%3};"
        : "+f"(c[0]), "+f"(c[1]), "+f"(c[2]), "+f"(c[3])
        : "r"(a[0]), "r"(a[1]), "r"(a[2]), "r"(a[3]), "r"(b0), "r"(b1));
}
__device__ __forceinline__ void cpa16(uint32_t dst, const void* src, int srcsize) {
    asm volatile("cp.async.cg.shared.global [%0], [%1], 16, %2;"
                 :: "r"(dst), "l"(src), "r"(srcsize));
}
__device__ __forceinline__ void cpa_commit() {
    asm volatile("cp.async.commit_group;" ::: "memory");
}
template <int NN>
__device__ __forceinline__ void cpa_wait() {
    asm volatile("cp.async.wait_group %0;" :: "n"(NN) : "memory");
}

// ---------------------------------------------------------------------------
// merged prep kernel: wt2 | wa | amh | bcw by blockIdx range
// ---------------------------------------------------------------------------
#define PREP_WT2_BLKS 2304           // 589824 / 256
#define PREP_WA_BLKS  768            // 196608 / 256
#define PREP_AMH_BLKS 10             // 2560 / 256
#define PREP_BLKS (PREP_WT2_BLKS + PREP_WA_BLKS + PREP_AMH_BLKS + 1)

__global__ void prep_kernel(const float* __restrict__ tw, const float* __restrict__ cw,
                            const float* __restrict__ A, const float* __restrict__ Mm,
                            const float* __restrict__ bias) {
    const int b = blockIdx.x;
    const int tid = threadIdx.x;
    if (b < PREP_WT2_BLKS) {
        int i = b * 256 + tid;
        if (i < TK_ * C_ * C_) {
            int dt = i / (C_ * C_);
            int r  = i - dt * C_ * C_;
            int co = r >> 8;
            int ci = r & 255;
            wt2_buf[i] = __float2half_rn(tw[(co * C_ + ci) * TK_ + dt]);
        }
    } else if (b < PREP_WT2_BLKS + PREP_WA_BLKS) {
        int i = (b - PREP_WT2_BLKS) * 256 + tid;
        if (i < C_ * KD1) {
            int co = i / KD1;
            int kk = i - co * KD1;
            int k  = kk >> 8;
            int ci = kk & 255;
            wa_buf[i] = __float2half_rn(cw[(k * C_ + co) * C_ + ci]);
        }
    } else if (b < PREP_WT2_BLKS + PREP_WA_BLKS + PREP_AMH_BLKS) {
        int i = (b - PREP_WT2_BLKS - PREP_WA_BLKS) * 256 + tid;
        if (i < 80 * 32) {
            int r = i >> 5;
            int v = i & 31;
            float val = 0.f;
            if (r < 75 && v < V_) {
                int k = r / V_;
                int w = r - k * V_;
                int idx = (k * V_ + v) * V_ + w;
                val = A[idx] * Mm[idx];
            }
            amh_buf[i] = __float2half_rn(val);
        }
    } else {
        __shared__ float S[K_ * V_];
        if (tid < K_ * V_) {
            int k = tid / V_;
            int w = tid - k * V_;
            float s = 0.f;
            for (int v = 0; v < V_; ++v) {
                int idx = (k * V_ + v) * V_ + w;
                s += A[idx] * Mm[idx];
            }
            S[tid] = s;
        }
        __syncthreads();
        int c = tid;
        for (int w = 0; w < V_; ++w) {
            float s = 0.f;
            #pragma unroll
            for (int k = 0; k < K_; ++k)
                s += bias[k * C_ + c] * S[k * V_ + w];
            bcw_buf[c * V_ + w] = s;
        }
    }
}

// ---------------------------------------------------------------------------
// xa via MMA, 4 t's per block: per (n, t0..t0+3):
//   D_t[(k,w)=75][ci=256] = AMh[75x32] . xB_t[256x32]^T
// B smem: 256 ci rows x (4 t-chunks x 32 halfs), stride 272B.
// x loads: 100 contiguous floats per ci (4t x 25v), float4 coalesced.
// Direct half2 writeout from accumulators (no smem transpose).
// ---------------------------------------------------------------------------
#define XAT 320
#define XB_STRIDE_H 136              // halfs per ci row (272B)
#define XB_BYTES (256 * 272)         // 69632
#define XA_AOFF XB_BYTES
#define XA_SMEM3 (XB_BYTES + 80 * 80)   // 76032

__global__ void __launch_bounds__(XAT, 2) xa_mma_kernel(const float* __restrict__ x)
{
    extern __shared__ char sxm[];
    const uint32_t sb = smem_u32(sxm);
    const int tid  = threadIdx.x;
    const int lane = tid & 31;
    const int wid  = tid >> 5;       // 0..9
    const int s    = wid >> 1;       // m-slice 0..4
    const int h    = wid & 1;        // n-half 0..1
    const int t0   = blockIdx.x * 4;
    const int n    = blockIdx.y;

    // zero the v=25..31 pad columns of every (ci, tc) chunk
    for (int i = tid; i < 256 * 28; i += XAT) {
        const int row = i / 28;
        const int r   = i - row * 28;
        const int tc  = r / 7;
        const int v   = 25 + (r - tc * 7);
        *(__half*)(sxm + row * 272 + (tc * 32 + v) * 2) = __half(0);
    }
    // load A tile (80 rows x 64B) -> smem @ XA_AOFF, stride 80B
    {
        uint4 v = ((const uint4*)amh_buf)[tid];
        *(uint4*)(sxm + XA_AOFF + (tid >> 2) * 80 + (tid & 3) * 16) = v;
    }
    // load x: per ci row, 100 contiguous floats (t0..t0+3 x 25v), float4.
    // base offset ((n*256+ci)*300 + t0)*25 floats; t0 % 4 == 0 -> 16B aligned.
    const float* xb = x + ((size_t)(n * C_) * T_ + t0) * V_;
    for (int i = tid; i < 256 * 25; i += XAT) {
        const int row = i / 25;
        const int f4  = i - row * 25;
        const float4 v = *(const float4*)(xb + (size_t)row * (T_ * V_) + f4 * 4);
        const int e0 = f4 * 4;
        #pragma unroll
        for (int e = 0; e < 4; ++e) {
            const int tc = (e0 + e) / 25;
            const int vv = (e0 + e) - tc * 25;
            const float f = (e == 0) ? v.x : (e == 1) ? v.y : (e == 2) ? v.z : v.w;
            *(__half*)(sxm + row * 272 + (tc * 32 + vv) * 2) = __float2half_rn(f);
        }
    }
    __syncthreads();

    // A fragments (once, reused for all 4 t's)
    uint32_t aa[2][4];
    {
        const uint32_t abase = sb + XA_AOFF + (uint32_t)((s * 16 + (lane & 15)) * 80)
                               + (uint32_t)((lane >> 4) << 4);
        ldsm4(aa[0], abase);        // k 0..15
        ldsm4(aa[1], abase + 32);   // k 16..31
    }

    const uint32_t brow0 = sb + (uint32_t)((h * 128 + (lane & 7) + (((lane >> 4) & 1) << 3)) * 272)
                           + (uint32_t)(((lane >> 3) & 1) << 4);

    for (int tc = 0; tc < 4; ++tc) {
        float acc[16][4];
        #pragma unroll
        for (int nf = 0; nf < 16; ++nf)
            #pragma unroll
            for (int q = 0; q < 4; ++q) acc[nf][q] = 0.f;

        const uint32_t bt = brow0 + (uint32_t)(tc * 64);
        #pragma unroll
        for (int ks = 0; ks < 2; ++ks) {
            #pragma unroll
            for (int nb = 0; nb < 8; ++nb) {
                uint32_t bb[4];
                ldsm4(bb, bt + (uint32_t)(nb * 16 * 272) + (uint32_t)(ks * 32));
                mma16816(acc[nb * 2 + 0], aa[ks], bb[0], bb[1]);
                mma16816(acc[nb * 2 + 1], aa[ks], bb[2], bb[3]);
            }
        }

        // direct writeout: row=(k,w) 0..74, col=ci
        __half* outb = xa_buf + ((size_t)n * J_ + (size_t)(t0 + tc) * V_) * KD1;
        #pragma unroll
        for (int hh = 0; hh < 2; ++hh) {
            const int row = s * 16 + (lane >> 2) + hh * 8;
            if (row < 75) {
                const int k = row / V_;
                const int w = row - k * V_;
                __half* orow = outb + (size_t)w * KD1 + k * C_ + h * 128 + (lane & 3) * 2;
                #pragma unroll
                for (int nf = 0; nf < 16; ++nf) {
                    __half2 p = __floats2half2_rn(acc[nf][hh * 2 + 0], acc[nf][hh * 2 + 1]);
                    *(__half2*)(orow + nf * 8) = p;
                }
            }
        }
    }
}

// ---------------------------------------------------------------------------
// GEMM1: sgc = Wa @ xa  -> BN1+ReLU+bcw -> gt[n][j][c] fp16   (proven)
// ---------------------------------------------------------------------------
#define G_STAGE 32768
#define G_SMEM  98304
#define IT1 12

__global__ void __launch_bounds__(256, 2) gemm1_kernel(
    const float* __restrict__ g1, const float* __restrict__ b1,
    const float* __restrict__ m1, const float* __restrict__ v1)
{
    extern __shared__ char smraw[];
    const uint32_t sb = smem_u32(smraw);
    const int tid  = threadIdx.x;
    const int wid  = tid >> 5;
    const int lane = tid & 31;
    const int j0   = blockIdx.x * 128;
    const int co0  = blockIdx.y * 128;
    const int n    = blockIdx.z;
    const int cw = (wid & 3) * 32;
    const int jw = (wid >> 2) * 64;

    const __half* xan = xa_buf + (size_t)n * J_ * KD1;

    float acc[2][8][4];
    #pragma unroll
    for (int mi = 0; mi < 2; ++mi)
        #pragma unroll
        for (int nf = 0; nf < 8; ++nf)
            #pragma unroll
            for (int q = 0; q < 4; ++q) acc[mi][nf][q] = 0.f;

    auto load_stage = [&](int it, int slot) {
        const uint32_t base = sb + (uint32_t)slot * G_STAGE;
        const int kb = it * 64;
        #pragma unroll
        for (int q = 0; q < 4; ++q) {
            const int c   = tid + q * 256;
            const int row = c >> 3;
            const int ch  = c & 7;
            const uint32_t sw = (uint32_t)((ch ^ (row & 7)) << 4);
            const __half* as = wa_buf + (size_t)(co0 + row) * KD1 + kb + ch * 8;
            cpa16(base + row * 128 + sw, as, 16);
            const int jp = j0 + row;
            const bool v = jp < J_;
            const __half* bs = xan + (size_t)(v ? jp : 0) * KD1 + kb + ch * 8;
            cpa16(base + 16384 + row * 128 + sw, bs, v ? 16 : 0);
        }
        cpa_commit();
    };

    load_stage(0, 0);
    load_stage(1, 1);

    const int rs  = lane & 7;
    const int hiA = lane >> 4;
    const int hiB = (lane >> 3) & 1;
    uint32_t rowA[2], rowB[4];
    #pragma unroll
    for (int mi = 0; mi < 2; ++mi)
        rowA[mi] = (uint32_t)((cw + mi * 16 + (lane & 15)) * 128);
    #pragma unroll
    for (int nb = 0; nb < 4; ++nb)
        rowB[nb] = (uint32_t)((jw + nb * 16 + (lane & 7) + (((lane >> 4) & 1) << 3)) * 128 + 16384);

    int wslot = 2, cslot = 0;
    for (int it = 0; it < IT1; ++it) {
        if (it < IT1 - 1) cpa_wait<1>(); else cpa_wait<0>();
        __syncthreads();
        if (it + 2 < IT1) {
            load_stage(it + 2, wslot);
            wslot = (wslot == 2) ? 0 : wslot + 1;
        }
        const uint32_t base = sb + (uint32_t)cslot * G_STAGE;
        cslot = (cslot == 2) ? 0 : cslot + 1;
        #pragma unroll
        for (int ks = 0; ks < 4; ++ks) {
            uint32_t aa[2][4], bb[4][4];
            #pragma unroll
            for (int mi = 0; mi < 2; ++mi)
                ldsm4(aa[mi], base + rowA[mi] + (uint32_t)((((ks * 2 + hiA) ^ rs)) << 4));
            #pragma unroll
            for (int nb = 0; nb < 4; ++nb)
                ldsm4(bb[nb], base + rowB[nb] + (uint32_t)((((ks * 2 + hiB) ^ rs)) << 4));
            #pragma unroll
            for (int mi = 0; mi < 2; ++mi)
                #pragma unroll
                for (int nf = 0; nf < 8; ++nf) {
                    const int nb = nf >> 1;
                    if (nf & 1) mma16816(acc[mi][nf], aa[mi], bb[nb][2], bb[nb][3]);
                    else        mma16816(acc[mi][nf], aa[mi], bb[nb][0], bb[nb][1]);
                }
        }
    }
    __syncthreads();

    // epilogue: bcw + BN1 + ReLU -> smem transpose tile -> gt
    __half* ts = (__half*)smraw;   // [128][136]
    #pragma unroll
    for (int mi = 0; mi < 2; ++mi) {
        #pragma unroll
        for (int hh = 0; hh < 2; ++hh) {
            const int col = cw + mi * 16 + (lane >> 2) + hh * 8;
            const int cog = co0 + col;
            const float scl = g1[cog] * rsqrtf(v1[cog] + BN_EPS);
            const float shf = b1[cog] - m1[cog] * scl;
            const float* bcr = bcw_buf + cog * V_;
            #pragma unroll
            for (int nf = 0; nf < 8; ++nf) {
                const int jl = jw + nf * 8 + (lane & 3) * 2;
                const int jg = j0 + jl;
                const int w0 = jg % 25;
                const int w1 = (w0 == 24) ? 0 : w0 + 1;
                float r0 = acc[mi][nf][hh * 2 + 0] + bcr[w0];
                float r1 = acc[mi][nf][hh * 2 + 1] + bcr[w1];
                r0 = fmaf(r0, scl, shf);
                r1 = fmaf(r1, scl, shf);
                r0 = r0 > 0.f ? r0 : 0.f;
                r1 = r1 > 0.f ? r1 : 0.f;
                ts[jl * 136 + col]       = __float2half_rn(r0);
                ts[(jl + 1) * 136 + col] = __float2half_rn(r1);
            }
        }
    }
    __syncthreads();

    __half* gout = gt_buf + (size_t)n * J_ * C_;
    #pragma unroll
    for (int p = 0; p < 8; ++p) {
        const int idx = p * 256 + tid;
        const int cc = idx & 15;
        const int j  = idx >> 4;
        const int jg = j0 + j;
        if (jg < J_) {
            uint4 vv = *(const uint4*)(ts + j * 136 + cc * 8);
            *(uint4*)(gout + (size_t)jg * C_ + co0 + cc * 8) = vv;
        }
    }
}

// ---------------------------------------------------------------------------
// GEMM2 (proven round-4 version): temporal conv + BN2 + ReLU + residual
// ---------------------------------------------------------------------------
#define IT2 36

__global__ void __launch_bounds__(256, 2) gemm2_kernel(
    const float* __restrict__ x, const float* __restrict__ tcb,
    const float* __restrict__ g2, const float* __restrict__ b2,
    const float* __restrict__ m2, const float* __restrict__ v2,
    float* __restrict__ out)
{
    extern __shared__ char smraw2[];
    const uint32_t sb = smem_u32(smraw2);
    const int tid  = threadIdx.x;
    const int wid  = tid >> 5;
    const int lane = tid & 31;
    const int j0   = blockIdx.x * 128;
    const int co0  = blockIdx.y * 128;
    const int n    = blockIdx.z;
    const int cw = (wid & 3) * 32;
    const int jw = (wid >> 2) * 64;

    const __half* gtn = gt_buf + (size_t)n * J_ * C_;

    float acc[2][8][4];
    #pragma unroll
    for (int mi = 0; mi < 2; ++mi)
        #pragma unroll
        for (int nf = 0; nf < 8; ++nf)
            #pragma unroll
            for (int q = 0; q < 4; ++q) acc[mi][nf][q] = 0.f;

    auto load_stage = [&](int it, int slot) {
        const uint32_t base = sb + (uint32_t)slot * G_STAGE;
        const int dt  = it >> 2;
        const int cic = (it & 3) << 6;
        const int s   = (dt - (TK_ - 1) / 2) * V_;
        #pragma unroll
        for (int q = 0; q < 4; ++q) {
            const int c   = tid + q * 256;
            const int row = c >> 3;
            const int ch  = c & 7;
            const uint32_t sw = (uint32_t)((ch ^ (row & 7)) << 4);
            const __half* as = wt2_buf + (size_t)dt * (C_ * C_) +
                               (size_t)(co0 + row) * C_ + cic + ch * 8;
            cpa16(base + row * 128 + sw, as, 16);
            const int jp = j0 + row + s;
            const bool v = (jp >= 0) && (jp < J_);
            const __half* bs = gtn + (size_t)(v ? jp : 0) * C_ + cic + ch * 8;
            cpa16(base + 16384 + row * 128 + sw, bs, v ? 16 : 0);
        }
        cpa_commit();
    };

    load_stage(0, 0);
    load_stage(1, 1);

    const int rs  = lane & 7;
    const int hiA = lane >> 4;
    const int hiB = (lane >> 3) & 1;
    uint32_t rowA[2], rowB[4];
    #pragma unroll
    for (int mi = 0; mi < 2; ++mi)
        rowA[mi] = (uint32_t)((cw + mi * 16 + (lane & 15)) * 128);
    #pragma unroll
    for (int nb = 0; nb < 4; ++nb)
        rowB[nb] = (uint32_t)((jw + nb * 16 + (lane & 7) + (((lane >> 4) & 1) << 3)) * 128 + 16384);

    int wslot = 2, cslot = 0;
    for (int it = 0; it < IT2; ++it) {
        if (it < IT2 - 1) cpa_wait<1>(); else cpa_wait<0>();
        __syncthreads();
        if (it + 2 < IT2) {
            load_stage(it + 2, wslot);
            wslot = (wslot == 2) ? 0 : wslot + 1;
        }
        const uint32_t base = sb + (uint32_t)cslot * G_STAGE;
        cslot = (cslot == 2) ? 0 : cslot + 1;
        #pragma unroll
        for (int ks = 0; ks < 4; ++ks) {
            uint32_t aa[2][4], bb[4][4];
            #pragma unroll
            for (int mi = 0; mi < 2; ++mi)
                ldsm4(aa[mi], base + rowA[mi] + (uint32_t)((((ks * 2 + hiA) ^ rs)) << 4));
            #pragma unroll
            for (int nb = 0; nb < 4; ++nb)
                ldsm4(bb[nb], base + rowB[nb] + (uint32_t)((((ks * 2 + hiB) ^ rs)) << 4));
            #pragma unroll
            for (int mi = 0; mi < 2; ++mi)
                #pragma unroll
                for (int nf = 0; nf < 8; ++nf) {
                    const int nb = nf >> 1;
                    if (nf & 1) mma16816(acc[mi][nf], aa[mi], bb[nb][2], bb[nb][3]);
                    else        mma16816(acc[mi][nf], aa[mi], bb[nb][0], bb[nb][1]);
                }
        }
    }

    // epilogue: BN2 + ReLU + residual
    #pragma unroll
    for (int mi = 0; mi < 2; ++mi) {
        #pragma unroll
        for (int hh = 0; hh < 2; ++hh) {
            const int co = co0 + cw + mi * 16 + (lane >> 2) + hh * 8;
            const float scl = g2[co] * rsqrtf(v2[co] + BN_EPS);
            const float shf = b2[co] - m2[co] * scl + tcb[co] * scl;
            const float* xr = x   + (size_t)(n * C_ + co) * J_;
            float* orow     = out + (size_t)(n * C_ + co) * J_;
            #pragma unroll
            for (int nf = 0; nf < 8; ++nf) {
                const int jj = j0 + jw + nf * 8 + (lane & 3) * 2;
                if (jj < J_) {
                    float v0 = fmaf(acc[mi][nf][hh * 2 + 0], scl, shf);
                    float v1 = fmaf(acc[mi][nf][hh * 2 + 1], scl, shf);
                    v0 = v0 > 0.f ? v0 : 0.f;
                    v1 = v1 > 0.f ? v1 : 0.f;
                    float2 xv = *(const float2*)(xr + jj);
                    float2 o;
                    o.x = v0 + xv.x;
                    o.y = v1 + xv.y;
                    *(float2*)(orow + jj) = o;
                }
            }
        }
    }
}

// ---------------------------------------------------------------------------
extern "C" void kernel_launch(void* const* d_in, const int* in_sizes, int n_in,
                              void* d_out, int out_size)
{
    const float* x   = (const float*)d_in[0];
    const float* A   = (const float*)d_in[1];
    // d_in[2] = att_A (unused)
    const float* Mm  = (const float*)d_in[3];
    const float* W   = (const float*)d_in[4];
    const float* cb  = (const float*)d_in[5];
    const float* g1  = (const float*)d_in[6];
    const float* b1  = (const float*)d_in[7];
    const float* m1  = (const float*)d_in[8];
    const float* v1  = (const float*)d_in[9];
    const float* tw  = (const float*)d_in[10];
    const float* tcb = (const float*)d_in[11];
    const float* g2  = (const float*)d_in[12];
    const float* b2  = (const float*)d_in[13];
    const float* m2  = (const float*)d_in[14];
    const float* v2  = (const float*)d_in[15];
    float* out = (float*)d_out;

    cudaFuncSetAttribute(xa_mma_kernel, cudaFuncAttributeMaxDynamicSharedMemorySize, XA_SMEM3);
    cudaFuncSetAttribute(gemm1_kernel,  cudaFuncAttributeMaxDynamicSharedMemorySize, G_SMEM);
    cudaFuncSetAttribute(gemm2_kernel,  cudaFuncAttributeMaxDynamicSharedMemorySize, G_SMEM);

    // merged prep (wt2 | wa | amh | bcw)
    prep_kernel<<<PREP_BLKS, 256>>>(tw, W, A, Mm, cb);

    // xa via MMA, 4 t's per block
    dim3 gxa(T_ / 4, N_);
    xa_mma_kernel<<<gxa, XAT, XA_SMEM3>>>(x);

    // GEMM1: S_GC + BN1 + ReLU -> gt
    dim3 gg1((J_ + 127) / 128, C_ / 128, N_);
    gemm1_kernel<<<gg1, 256, G_SMEM>>>(g1, b1, m1, v1);

    // GEMM2: temporal conv + BN2 + ReLU + residual
    dim3 gg2((J_ + 127) / 128, C_ / 128, N_);
    gemm2_kernel<<<gg2, 256, G_SMEM>>>(x, tcb, g2, b2, m2, v2, out);
}